// round 4
// baseline (speedup 1.0000x reference)
#include <cuda_runtime.h>
#include <cuda_fp16.h>
#include <cstdint>
#include <math.h>

// ---------------- Problem constants ----------------
#define D_DIM 4096
#define S_DIM 2048
#define B_DIM 4
#define K_EXP 8
#define R_DIM 16
#define KR    128
#define T_TOK 8192
#define SCALE 2.0f

// ---------------- Device scratch (static; no runtime alloc) ----------------
__device__ __align__(16) float  g_partial[B_DIM * 8 * D_DIM];
__device__ float  g_weights[B_DIM * K_EXP];
__device__ __align__(16) __half g_xh[(size_t)T_TOK * D_DIM];          // 64 MB
__device__ __align__(16) __half g_wh[(size_t)D_DIM * D_DIM];          // 32 MB
__device__ __align__(16) __half g_ah[(size_t)KR * D_DIM];             //  1 MB
__device__ __align__(16) __half g_Bwh[(size_t)B_DIM * D_DIM * KR];    //  4 MB
__device__ __align__(16) __half g_hh[(size_t)T_TOK * KR];             //  2 MB

// ---------------- PTX helpers ----------------
__device__ __forceinline__ uint32_t smem_u32(const void* p) {
    uint32_t a;
    asm("{ .reg .u64 t; cvta.to.shared.u64 t, %1; cvt.u32.u64 %0, t; }"
        : "=r"(a) : "l"(p));
    return a;
}

#define CP_ASYNC16(dst, src) \
    asm volatile("cp.async.cg.shared.global [%0], [%1], 16;" \
                 :: "r"(dst), "l"(src) : "memory")
#define CP_COMMIT() asm volatile("cp.async.commit_group;" ::: "memory")
#define CP_WAIT(n)  asm volatile("cp.async.wait_group %0;" :: "n"(n) : "memory")

#define LDSM4(r0, r1, r2, r3, addr) \
    asm volatile("ldmatrix.sync.aligned.m8n8.x4.shared.b16 {%0,%1,%2,%3}, [%4];" \
                 : "=r"(r0), "=r"(r1), "=r"(r2), "=r"(r3) : "r"(addr))

#define MMA16816(d, a, b) \
    asm volatile("mma.sync.aligned.m16n8k16.row.col.f32.f16.f16.f32 " \
                 "{%0,%1,%2,%3},{%4,%5,%6,%7},{%8,%9},{%0,%1,%2,%3};" \
                 : "+f"((d)[0]), "+f"((d)[1]), "+f"((d)[2]), "+f"((d)[3]) \
                 : "r"((a)[0]), "r"((a)[1]), "r"((a)[2]), "r"((a)[3]), \
                   "r"((b)[0]), "r"((b)[1]))

// Swizzled smem addr: rows of 32 halfs (64 B), 4 x 16B chunks, ch ^= (row>>1)&3
__device__ __forceinline__ uint32_t sw_addr(uint32_t base, int row, int ch) {
    return base + row * 64 + ((uint32_t)(ch ^ ((row >> 1) & 3)) << 4);
}

// ---------------------------------------------------------------------------
// Aux kernels
// ---------------------------------------------------------------------------
__global__ void cvt_f2h_kernel(const float* __restrict__ s, __half* __restrict__ d) {
    size_t i = ((size_t)blockIdx.x * 256 + threadIdx.x) * 4;
    float4 v = *(const float4*)(s + i);
    *(__half2*)(d + i)     = __floats2half2_rn(v.x, v.y);
    *(__half2*)(d + i + 2) = __floats2half2_rn(v.z, v.w);
}

// column partial sums of x (fp16 source, fp32 accum), 256-row chunks
__global__ void mean_partial_h_kernel(const __half* __restrict__ xh) {
    int d = blockIdx.x * 256 + threadIdx.x;     // two halfs per thread
    int b = blockIdx.y;
    int c = blockIdx.z;
    const __half* p = xh + ((size_t)(b * S_DIM + c * 256)) * D_DIM + 2 * d;
    float s0 = 0.f, s1 = 0.f;
#pragma unroll 8
    for (int i = 0; i < 256; i++) {
        __half2 h = *(const __half2*)(p + (size_t)i * D_DIM);
        float2 f = __half22float2(h);
        s0 += f.x; s1 += f.y;
    }
    g_partial[(b * 8 + c) * D_DIM + 2 * d]     = s0;
    g_partial[(b * 8 + c) * D_DIM + 2 * d + 1] = s1;
}

__global__ void router_kernel(const float* __restrict__ rw, const float* __restrict__ rb) {
    int b = blockIdx.x;
    int tid = threadIdx.x;
    float acc[K_EXP];
#pragma unroll
    for (int k = 0; k < K_EXP; k++) acc[k] = 0.f;

    for (int d = tid; d < D_DIM; d += 256) {
        float m = 0.f;
#pragma unroll
        for (int c = 0; c < 8; c++) m += g_partial[(b * 8 + c) * D_DIM + d];
        m *= (1.0f / (float)S_DIM);
#pragma unroll
        for (int k = 0; k < K_EXP; k++) acc[k] += m * rw[k * D_DIM + d];
    }

    __shared__ float red[K_EXP][256];
#pragma unroll
    for (int k = 0; k < K_EXP; k++) red[k][tid] = acc[k];
    __syncthreads();

    if (tid < K_EXP) {
        float s = 0.f;
        for (int i = 0; i < 256; i++) s += red[tid][i];
        red[tid][0] = s + rb[tid];
    }
    __syncthreads();

    if (tid == 0) {
        float mx = -1e30f;
#pragma unroll
        for (int k = 0; k < K_EXP; k++) mx = fmaxf(mx, red[k][0]);
        float e[K_EXP], sum = 0.f;
#pragma unroll
        for (int k = 0; k < K_EXP; k++) { e[k] = expf(red[k][0] - mx); sum += e[k]; }
        float inv = 1.0f / sum;
#pragma unroll
        for (int k = 0; k < K_EXP; k++) g_weights[b * K_EXP + k] = e[k] * inv;
    }
}

__global__ void bw_kernel(const float* __restrict__ loraB) {
    int idx = blockIdx.x * 256 + threadIdx.x;           // < 2^21
    int b   = idx >> 19;
    int rem = idx & ((1 << 19) - 1);
    int o   = rem >> 7;
    int c   = rem & 127;
    int k   = c >> 4;
    int r   = c & 15;
    float v = SCALE * g_weights[b * K_EXP + k] * loraB[(k * D_DIM + o) * R_DIM + r];
    g_Bwh[idx] = __float2half_rn(v);
}

// ---------------------------------------------------------------------------
// Pipelined fp16 mma.sync GEMM, templated tile.
//   C[i,j] = sum_k A[i,k]*Bm[j,k]  (+ EXT: sum_c A2[i,c]*B2[b(i),j,c]) (+ bias[j])
// Warp tile 64x32; WARPS = (BM/64) x (BN/32); BK=32; 4-stage cp.async.
// ---------------------------------------------------------------------------
template <int BM, int BN, bool EXT, bool BIAS, bool OUTH>
__global__ void __launch_bounds__((BM / 64) * (BN / 32) * 32, 1) mma_gemm_kernel(
    const __half* __restrict__ A, int lda,
    const __half* __restrict__ Bm, int ldb,
    const __half* __restrict__ A2,
    const __half* __restrict__ B2all,
    const float* __restrict__ bias,
    float* __restrict__ outf, __half* __restrict__ outh,
    int ldc, int iters0, int iters)
{
    constexpr int WM = BM / 64;
    constexpr int WN = BN / 32;
    constexpr int THREADS = WM * WN * 32;
    constexpr int ABYT = BM * 64;            // bytes per A stage
    constexpr int STG  = (BM + BN) * 64;     // bytes per stage

    extern __shared__ __align__(128) char smem[];
    const uint32_t sbase = smem_u32(smem);
    const int tid  = threadIdx.x;
    const int lane = tid & 31;
    const int wid  = tid >> 5;
    const int wm   = wid % WM;
    const int wn   = wid / WM;
    const int i0   = blockIdx.y * BM;
    const int j0   = blockIdx.x * BN;
    const __half* B2 = nullptr;
    if (EXT) B2 = B2all + (size_t)(i0 >> 11) * ((size_t)D_DIM * KR);

    auto loadst = [&](int git, int st) {
        uint32_t abase = sbase + st * STG;
        uint32_t bbase = abase + ABYT;
        bool ph0 = (!EXT || git < iters0);
        int koff = ph0 ? git * 32 : (git - iters0) * 32;
#pragma unroll
        for (int t = 0; t < (BM * 4) / THREADS; t++) {
            int idx = tid + t * THREADS;
            int row = idx >> 2, ch = idx & 3;
            const __half* src = ph0
                ? A  + (size_t)(i0 + row) * lda + koff + ch * 8
                : A2 + (size_t)(i0 + row) * KR  + koff + ch * 8;
            CP_ASYNC16(sw_addr(abase, row, ch), src);
        }
#pragma unroll
        for (int t = 0; t < (BN * 4) / THREADS; t++) {
            int idx = tid + t * THREADS;
            int row = idx >> 2, ch = idx & 3;
            const __half* src = ph0
                ? Bm + (size_t)(j0 + row) * ldb + koff + ch * 8
                : B2 + (size_t)(j0 + row) * KR  + koff + ch * 8;
            CP_ASYNC16(sw_addr(bbase, row, ch), src);
        }
    };

    float acc[4][4][4];
#pragma unroll
    for (int mi = 0; mi < 4; mi++)
#pragma unroll
        for (int ni = 0; ni < 4; ni++)
#pragma unroll
            for (int e = 0; e < 4; e++) acc[mi][ni][e] = 0.f;

#pragma unroll
    for (int s = 0; s < 3; s++) { loadst(s, s); CP_COMMIT(); }

    for (int it = 0; it < iters; ++it) {
        CP_WAIT(2);
        __syncthreads();
        if (it + 3 < iters) loadst(it + 3, (it + 3) & 3);
        CP_COMMIT();

        uint32_t sA = sbase + (it & 3) * STG;
        uint32_t sB = sA + ABYT;
#pragma unroll
        for (int ks = 0; ks < 2; ks++) {
            int ch = ks * 2 + (lane >> 4);
            uint32_t a[4][4];
#pragma unroll
            for (int mi = 0; mi < 4; mi++) {
                int row = wm * 64 + mi * 16 + (lane & 15);
                LDSM4(a[mi][0], a[mi][1], a[mi][2], a[mi][3], sw_addr(sA, row, ch));
            }
            uint32_t b[4][2];
#pragma unroll
            for (int j = 0; j < 2; j++) {
                int row = wn * 32 + j * 16 + (lane & 15);
                uint32_t t0, t1, t2, t3;
                LDSM4(t0, t1, t2, t3, sw_addr(sB, row, ch));
                b[2 * j][0]     = t0; b[2 * j][1]     = t2;
                b[2 * j + 1][0] = t1; b[2 * j + 1][1] = t3;
            }
#pragma unroll
            for (int mi = 0; mi < 4; mi++)
#pragma unroll
                for (int ni = 0; ni < 4; ni++)
                    MMA16816(acc[mi][ni], a[mi], b[ni]);
        }
    }

    // epilogue
#pragma unroll
    for (int mi = 0; mi < 4; mi++) {
        int r0 = i0 + wm * 64 + mi * 16 + (lane >> 2);
#pragma unroll
        for (int ni = 0; ni < 4; ni++) {
            int c0 = j0 + wn * 32 + ni * 8 + 2 * (lane & 3);
            if (OUTH) {
                *(__half2*)(outh + (size_t)r0 * ldc + c0) =
                    __floats2half2_rn(acc[mi][ni][0], acc[mi][ni][1]);
                *(__half2*)(outh + (size_t)(r0 + 8) * ldc + c0) =
                    __floats2half2_rn(acc[mi][ni][2], acc[mi][ni][3]);
            } else {
                float b0 = 0.f, b1 = 0.f;
                if (BIAS) { b0 = bias[c0]; b1 = bias[c0 + 1]; }
                float2 v0 = { acc[mi][ni][0] + b0, acc[mi][ni][1] + b1 };
                float2 v1 = { acc[mi][ni][2] + b0, acc[mi][ni][3] + b1 };
                *(float2*)(outf + (size_t)r0 * ldc + c0)       = v0;
                *(float2*)(outf + (size_t)(r0 + 8) * ldc + c0) = v1;
            }
        }
    }
}

// ---------------------------------------------------------------------------
extern "C" void kernel_launch(void* const* d_in, const int* in_sizes, int n_in,
                              void* d_out, int out_size) {
    const float* x      = (const float*)d_in[0];   // [4,2048,4096]
    const float* base_w = (const float*)d_in[1];   // [4096,4096]
    const float* base_b = (const float*)d_in[2];   // [4096]
    const float* lora_A = (const float*)d_in[3];   // [8,16,4096]
    const float* lora_B = (const float*)d_in[4];   // [8,4096,16]
    const float* rout_w = (const float*)d_in[5];   // [8,4096]
    const float* rout_b = (const float*)d_in[6];   // [8]
    float* out = (float*)d_out;

    // main: BM=256, BN=128 -> stage 24KB, 4 stages = 96KB, 512 threads
    const int SMEM_MAIN = 4 * (256 + 128) * 64;    // 98304
    // h:    BM=128, BN=128 -> stage 16KB, 4 stages = 64KB, 256 threads
    const int SMEM_H    = 4 * (128 + 128) * 64;    // 65536
    cudaFuncSetAttribute(mma_gemm_kernel<256, 128, true, true, false>,
                         cudaFuncAttributeMaxDynamicSharedMemorySize, SMEM_MAIN);
    cudaFuncSetAttribute(mma_gemm_kernel<128, 128, false, false, true>,
                         cudaFuncAttributeMaxDynamicSharedMemorySize, SMEM_H);

    __half* xh;  cudaGetSymbolAddress((void**)&xh,  g_xh);
    __half* wh;  cudaGetSymbolAddress((void**)&wh,  g_wh);
    __half* ah;  cudaGetSymbolAddress((void**)&ah,  g_ah);
    __half* bwh; cudaGetSymbolAddress((void**)&bwh, g_Bwh);
    __half* hh;  cudaGetSymbolAddress((void**)&hh,  g_hh);

    // fp32 -> fp16 conversions
    cvt_f2h_kernel<<<(T_TOK * (size_t)D_DIM) / 1024, 256>>>(x, xh);
    cvt_f2h_kernel<<<((size_t)D_DIM * D_DIM) / 1024, 256>>>(base_w, wh);
    cvt_f2h_kernel<<<((size_t)KR * D_DIM) / 1024, 256>>>(lora_A, ah);

    // router path (mean from fp16 x, fp32 accum)
    mean_partial_h_kernel<<<dim3(D_DIM / 512, B_DIM, 8), 256>>>(xh);
    router_kernel<<<B_DIM, 256>>>(rout_w, rout_b);
    bw_kernel<<<(B_DIM * D_DIM * KR) / 256, 256>>>(lora_B);

    // h = x @ A_cat^T  (M=8192, N=128, K=4096) -> g_hh (fp16)
    mma_gemm_kernel<128, 128, false, false, true><<<dim3(1, T_TOK / 128), 256, SMEM_H>>>(
        xh, D_DIM, ah, D_DIM, nullptr, nullptr, nullptr,
        nullptr, hh, KR, 128, 128);

    // out = x @ W^T + h @ Bw^T + bias  (K = 4096 + 128)
    mma_gemm_kernel<256, 128, true, true, false>
        <<<dim3(D_DIM / 128, T_TOK / 256), 512, SMEM_MAIN>>>(
        xh, D_DIM, wh, D_DIM, hh, bwh, base_b,
        out, nullptr, D_DIM, 128, 132);
}

// round 5
// speedup vs baseline: 1.1306x; 1.1306x over previous
#include <cuda_runtime.h>
#include <cuda_fp16.h>
#include <cstdint>
#include <math.h>

// ---------------- Problem constants ----------------
#define D_DIM 4096
#define S_DIM 2048
#define B_DIM 4
#define K_EXP 8
#define R_DIM 16
#define KR    128
#define T_TOK 8192
#define SCALE 2.0f

// ---------------- Device scratch (static; no runtime alloc) ----------------
__device__ __align__(16) float  g_partial[B_DIM * 8 * D_DIM];
__device__ float  g_weights[B_DIM * K_EXP];
__device__ __align__(16) __half g_xh[(size_t)T_TOK * D_DIM];          // 64 MB
__device__ __align__(16) __half g_wh[(size_t)D_DIM * D_DIM];          // 32 MB
__device__ __align__(16) __half g_ah[(size_t)KR * D_DIM];             //  1 MB
__device__ __align__(16) __half g_Bwh[(size_t)B_DIM * D_DIM * KR];    //  4 MB
__device__ __align__(16) __half g_hh[(size_t)T_TOK * KR];             //  2 MB

// ---------------- PTX helpers ----------------
__device__ __forceinline__ uint32_t smem_u32(const void* p) {
    uint32_t a;
    asm("{ .reg .u64 t; cvta.to.shared.u64 t, %1; cvt.u32.u64 %0, t; }"
        : "=r"(a) : "l"(p));
    return a;
}

#define CP_ASYNC16(dst, src) \
    asm volatile("cp.async.cg.shared.global [%0], [%1], 16;" \
                 :: "r"(dst), "l"(src) : "memory")
#define CP_COMMIT() asm volatile("cp.async.commit_group;" ::: "memory")
#define CP_WAIT(n)  asm volatile("cp.async.wait_group %0;" :: "n"(n) : "memory")

#define LDSM4(r0, r1, r2, r3, addr) \
    asm volatile("ldmatrix.sync.aligned.m8n8.x4.shared.b16 {%0,%1,%2,%3}, [%4];" \
                 : "=r"(r0), "=r"(r1), "=r"(r2), "=r"(r3) : "r"(addr))

#define MMA16816(d, a, b) \
    asm volatile("mma.sync.aligned.m16n8k16.row.col.f32.f16.f16.f32 " \
                 "{%0,%1,%2,%3},{%4,%5,%6,%7},{%8,%9},{%0,%1,%2,%3};" \
                 : "+f"((d)[0]), "+f"((d)[1]), "+f"((d)[2]), "+f"((d)[3]) \
                 : "r"((a)[0]), "r"((a)[1]), "r"((a)[2]), "r"((a)[3]), \
                   "r"((b)[0]), "r"((b)[1]))

// SW128 swizzle for 128-byte rows: off ^= (off>>3)&0x70
__device__ __forceinline__ uint32_t sw128(uint32_t base, int row, int ch) {
    uint32_t off = (uint32_t)(row * 128 + ch * 16);
    return base + (off ^ ((off >> 3) & 0x70));
}

// ---------------------------------------------------------------------------
// Aux kernels
// ---------------------------------------------------------------------------
__global__ void cvt_f2h_kernel(const float* __restrict__ s, __half* __restrict__ d) {
    size_t i = ((size_t)blockIdx.x * 256 + threadIdx.x) * 4;
    float4 v = *(const float4*)(s + i);
    *(__half2*)(d + i)     = __floats2half2_rn(v.x, v.y);
    *(__half2*)(d + i + 2) = __floats2half2_rn(v.z, v.w);
}

__global__ void mean_partial_h_kernel(const __half* __restrict__ xh) {
    int d = blockIdx.x * 256 + threadIdx.x;
    int b = blockIdx.y;
    int c = blockIdx.z;
    const __half* p = xh + ((size_t)(b * S_DIM + c * 256)) * D_DIM + 2 * d;
    float s0 = 0.f, s1 = 0.f;
#pragma unroll 8
    for (int i = 0; i < 256; i++) {
        float2 f = __half22float2(*(const __half2*)(p + (size_t)i * D_DIM));
        s0 += f.x; s1 += f.y;
    }
    g_partial[(b * 8 + c) * D_DIM + 2 * d]     = s0;
    g_partial[(b * 8 + c) * D_DIM + 2 * d + 1] = s1;
}

__global__ void router_kernel(const float* __restrict__ rw, const float* __restrict__ rb) {
    int b = blockIdx.x;
    int tid = threadIdx.x;
    float acc[K_EXP];
#pragma unroll
    for (int k = 0; k < K_EXP; k++) acc[k] = 0.f;

    for (int d = tid; d < D_DIM; d += 256) {
        float m = 0.f;
#pragma unroll
        for (int c = 0; c < 8; c++) m += g_partial[(b * 8 + c) * D_DIM + d];
        m *= (1.0f / (float)S_DIM);
#pragma unroll
        for (int k = 0; k < K_EXP; k++) acc[k] += m * rw[k * D_DIM + d];
    }

    __shared__ float red[K_EXP][256];
#pragma unroll
    for (int k = 0; k < K_EXP; k++) red[k][tid] = acc[k];
    __syncthreads();

    if (tid < K_EXP) {
        float s = 0.f;
        for (int i = 0; i < 256; i++) s += red[tid][i];
        red[tid][0] = s + rb[tid];
    }
    __syncthreads();

    if (tid == 0) {
        float mx = -1e30f;
#pragma unroll
        for (int k = 0; k < K_EXP; k++) mx = fmaxf(mx, red[k][0]);
        float e[K_EXP], sum = 0.f;
#pragma unroll
        for (int k = 0; k < K_EXP; k++) { e[k] = expf(red[k][0] - mx); sum += e[k]; }
        float inv = 1.0f / sum;
#pragma unroll
        for (int k = 0; k < K_EXP; k++) g_weights[b * K_EXP + k] = e[k] * inv;
    }
}

__global__ void bw_kernel(const float* __restrict__ loraB) {
    int idx = blockIdx.x * 256 + threadIdx.x;           // < 2^21
    int b   = idx >> 19;
    int rem = idx & ((1 << 19) - 1);
    int o   = rem >> 7;
    int c   = rem & 127;
    int k   = c >> 4;
    int r   = c & 15;
    float v = SCALE * g_weights[b * K_EXP + k] * loraB[(k * D_DIM + o) * R_DIM + r];
    g_Bwh[idx] = __float2half_rn(v);
}

// ---------------------------------------------------------------------------
// Pipelined fp16 mma.sync GEMM. BK=64, 3-stage cp.async, warp tile 64x32.
//   C[i,j] = sum_k A[i,k]*Bm[j,k]  (+ EXT: sum_c A2[i,c]*B2[b(i),j,c]) (+ bias[j])
// ---------------------------------------------------------------------------
template <int BM, int BN, bool EXT, bool BIAS, bool OUTH>
__global__ void __launch_bounds__((BM / 64) * (BN / 32) * 32, 2) mma_gemm_kernel(
    const __half* __restrict__ A, int lda,
    const __half* __restrict__ Bm, int ldb,
    const __half* __restrict__ A2,
    const __half* __restrict__ B2all,
    const float* __restrict__ bias,
    float* __restrict__ outf, __half* __restrict__ outh,
    int ldc, int iters0, int iters)
{
    constexpr int WM = BM / 64;
    constexpr int WN = BN / 32;
    constexpr int THREADS = WM * WN * 32;
    constexpr int ABYT = BM * 128;           // bytes per A stage (BK=64 halfs = 128B/row)
    constexpr int STG  = (BM + BN) * 128;    // bytes per stage

    extern __shared__ __align__(128) char smem[];
    const uint32_t sbase = smem_u32(smem);
    const int tid  = threadIdx.x;
    const int lane = tid & 31;
    const int wid  = tid >> 5;
    const int wm   = wid % WM;
    const int wn   = wid / WM;
    const int i0   = blockIdx.y * BM;
    const int j0   = blockIdx.x * BN;
    const __half* B2 = nullptr;
    if (EXT) B2 = B2all + (size_t)(i0 >> 11) * ((size_t)D_DIM * KR);

    auto loadst = [&](int git, int st) {
        uint32_t abase = sbase + st * STG;
        uint32_t bbase = abase + ABYT;
        bool ph0 = (!EXT || git < iters0);
        int koff = ph0 ? git * 64 : (git - iters0) * 64;
#pragma unroll
        for (int t = 0; t < (BM * 8) / THREADS; t++) {
            int idx = tid + t * THREADS;
            int row = idx >> 3, ch = idx & 7;
            const __half* src = ph0
                ? A  + (size_t)(i0 + row) * lda + koff + ch * 8
                : A2 + (size_t)(i0 + row) * KR  + koff + ch * 8;
            CP_ASYNC16(sw128(abase, row, ch), src);
        }
#pragma unroll
        for (int t = 0; t < (BN * 8) / THREADS; t++) {
            int idx = tid + t * THREADS;
            int row = idx >> 3, ch = idx & 7;
            const __half* src = ph0
                ? Bm + (size_t)(j0 + row) * ldb + koff + ch * 8
                : B2 + (size_t)(j0 + row) * KR  + koff + ch * 8;
            CP_ASYNC16(sw128(bbase, row, ch), src);
        }
    };

    float acc[4][4][4];
#pragma unroll
    for (int mi = 0; mi < 4; mi++)
#pragma unroll
        for (int ni = 0; ni < 4; ni++)
#pragma unroll
            for (int e = 0; e < 4; e++) acc[mi][ni][e] = 0.f;

    // prologue: 2 stages in flight (3-stage ring)
    loadst(0, 0); CP_COMMIT();
    loadst(1, 1); CP_COMMIT();

    int st = 0;                 // stage of iter it
    int pf = 2;                 // stage to prefetch into
    for (int it = 0; it < iters; ++it) {
        CP_WAIT(1);
        __syncthreads();
        if (it + 2 < iters) loadst(it + 2, pf);
        CP_COMMIT();

        uint32_t sA = sbase + st * STG;
        uint32_t sB = sA + ABYT;
#pragma unroll
        for (int ks = 0; ks < 4; ks++) {
            int ch = ks * 2 + (lane >> 4);
            uint32_t a[4][4];
#pragma unroll
            for (int mi = 0; mi < 4; mi++) {
                int row = wm * 64 + mi * 16 + (lane & 15);
                LDSM4(a[mi][0], a[mi][1], a[mi][2], a[mi][3], sw128(sA, row, ch));
            }
            uint32_t b[4][2];
#pragma unroll
            for (int j = 0; j < 2; j++) {
                int row = wn * 32 + j * 16 + (lane & 15);
                uint32_t t0, t1, t2, t3;
                LDSM4(t0, t1, t2, t3, sw128(sB, row, ch));
                b[2 * j][0]     = t0; b[2 * j][1]     = t2;
                b[2 * j + 1][0] = t1; b[2 * j + 1][1] = t3;
            }
#pragma unroll
            for (int mi = 0; mi < 4; mi++)
#pragma unroll
                for (int ni = 0; ni < 4; ni++)
                    MMA16816(acc[mi][ni], a[mi], b[ni]);
        }
        __syncthreads();
        st = (st == 2) ? 0 : st + 1;
        pf = (pf == 2) ? 0 : pf + 1;
    }

    // epilogue
#pragma unroll
    for (int mi = 0; mi < 4; mi++) {
        int r0 = i0 + wm * 64 + mi * 16 + (lane >> 2);
#pragma unroll
        for (int ni = 0; ni < 4; ni++) {
            int c0 = j0 + wn * 32 + ni * 8 + 2 * (lane & 3);
            if (OUTH) {
                *(__half2*)(outh + (size_t)r0 * ldc + c0) =
                    __floats2half2_rn(acc[mi][ni][0], acc[mi][ni][1]);
                *(__half2*)(outh + (size_t)(r0 + 8) * ldc + c0) =
                    __floats2half2_rn(acc[mi][ni][2], acc[mi][ni][3]);
            } else {
                float b0 = 0.f, b1 = 0.f;
                if (BIAS) { b0 = bias[c0]; b1 = bias[c0 + 1]; }
                float2 v0 = { acc[mi][ni][0] + b0, acc[mi][ni][1] + b1 };
                float2 v1 = { acc[mi][ni][2] + b0, acc[mi][ni][3] + b1 };
                *(float2*)(outf + (size_t)r0 * ldc + c0)       = v0;
                *(float2*)(outf + (size_t)(r0 + 8) * ldc + c0) = v1;
            }
        }
    }
}

// ---------------------------------------------------------------------------
extern "C" void kernel_launch(void* const* d_in, const int* in_sizes, int n_in,
                              void* d_out, int out_size) {
    const float* x      = (const float*)d_in[0];   // [4,2048,4096]
    const float* base_w = (const float*)d_in[1];   // [4096,4096]
    const float* base_b = (const float*)d_in[2];   // [4096]
    const float* lora_A = (const float*)d_in[3];   // [8,16,4096]
    const float* lora_B = (const float*)d_in[4];   // [8,4096,16]
    const float* rout_w = (const float*)d_in[5];   // [8,4096]
    const float* rout_b = (const float*)d_in[6];   // [8]
    float* out = (float*)d_out;

    // main: BM=128, BN=128, BK=64 -> stage 32KB x3 = 96KB, 256 threads, 2 CTA/SM
    const int SMEM_MAIN = 3 * (128 + 128) * 128;   // 98304
    // h: BM=64, BN=128 -> stage 24KB x3 = 72KB, 128 threads
    const int SMEM_H    = 3 * (64 + 128) * 128;    // 73728
    cudaFuncSetAttribute(mma_gemm_kernel<128, 128, true, true, false>,
                         cudaFuncAttributeMaxDynamicSharedMemorySize, SMEM_MAIN);
    cudaFuncSetAttribute(mma_gemm_kernel<64, 128, false, false, true>,
                         cudaFuncAttributeMaxDynamicSharedMemorySize, SMEM_H);

    __half* xh;  cudaGetSymbolAddress((void**)&xh,  g_xh);
    __half* wh;  cudaGetSymbolAddress((void**)&wh,  g_wh);
    __half* ah;  cudaGetSymbolAddress((void**)&ah,  g_ah);
    __half* bwh; cudaGetSymbolAddress((void**)&bwh, g_Bwh);
    __half* hh;  cudaGetSymbolAddress((void**)&hh,  g_hh);

    // fp32 -> fp16 conversions
    cvt_f2h_kernel<<<(T_TOK * (size_t)D_DIM) / 1024, 256>>>(x, xh);
    cvt_f2h_kernel<<<((size_t)D_DIM * D_DIM) / 1024, 256>>>(base_w, wh);
    cvt_f2h_kernel<<<((size_t)KR * D_DIM) / 1024, 256>>>(lora_A, ah);

    // router path (mean from fp16 x, fp32 accum)
    mean_partial_h_kernel<<<dim3(D_DIM / 512, B_DIM, 8), 256>>>(xh);
    router_kernel<<<B_DIM, 256>>>(rout_w, rout_b);
    bw_kernel<<<(B_DIM * D_DIM * KR) / 256, 256>>>(lora_B);

    // h = x @ A_cat^T  (M=8192, N=128, K=4096) -> g_hh (fp16)
    mma_gemm_kernel<64, 128, false, false, true>
        <<<dim3(1, T_TOK / 64), 128, SMEM_H>>>(
        xh, D_DIM, ah, D_DIM, nullptr, nullptr, nullptr,
        nullptr, hh, KR, 64, 64);

    // out = x @ W^T + h @ Bw^T + bias  (K = 4096 + 128 => 64+2 iters of 64)
    mma_gemm_kernel<128, 128, true, true, false>
        <<<dim3(D_DIM / 128, T_TOK / 128), 256, SMEM_MAIN>>>(
        xh, D_DIM, wh, D_DIM, hh, bwh, base_b,
        out, nullptr, D_DIM, 64, 66);
}

// round 6
// speedup vs baseline: 1.1424x; 1.0104x over previous
#include <cuda_runtime.h>
#include <cuda_fp16.h>
#include <cstdint>
#include <math.h>

// ---------------- Problem constants ----------------
#define D_DIM 4096
#define S_DIM 2048
#define B_DIM 4
#define K_EXP 8
#define R_DIM 16
#define KR    128
#define T_TOK 8192
#define SCALE 2.0f

// ---------------- Device scratch (static; no runtime alloc) ----------------
__device__ __align__(16) float  g_partial[B_DIM * 8 * D_DIM];
__device__ float  g_weights[B_DIM * K_EXP];
__device__ __align__(16) __half g_xh[(size_t)T_TOK * D_DIM];          // 64 MB
__device__ __align__(16) __half g_wh[(size_t)D_DIM * D_DIM];          // 32 MB
__device__ __align__(16) __half g_ah[(size_t)KR * D_DIM];             //  1 MB
__device__ __align__(16) __half g_Bwh[(size_t)B_DIM * D_DIM * KR];    //  4 MB
__device__ __align__(16) __half g_hh[(size_t)T_TOK * KR];             //  2 MB
__device__ __align__(16) float  g_hp[2][(size_t)T_TOK * KR];          //  8 MB fp32 partials

// ---------------- PTX helpers ----------------
__device__ __forceinline__ uint32_t smem_u32(const void* p) {
    uint32_t a;
    asm("{ .reg .u64 t; cvta.to.shared.u64 t, %1; cvt.u32.u64 %0, t; }"
        : "=r"(a) : "l"(p));
    return a;
}

#define CP_ASYNC16(dst, src) \
    asm volatile("cp.async.cg.shared.global [%0], [%1], 16;" \
                 :: "r"(dst), "l"(src) : "memory")
#define CP_COMMIT() asm volatile("cp.async.commit_group;" ::: "memory")
#define CP_WAIT(n)  asm volatile("cp.async.wait_group %0;" :: "n"(n) : "memory")

#define LDSM4(r0, r1, r2, r3, addr) \
    asm volatile("ldmatrix.sync.aligned.m8n8.x4.shared.b16 {%0,%1,%2,%3}, [%4];" \
                 : "=r"(r0), "=r"(r1), "=r"(r2), "=r"(r3) : "r"(addr))

#define MMA16816(d, a, b) \
    asm volatile("mma.sync.aligned.m16n8k16.row.col.f32.f16.f16.f32 " \
                 "{%0,%1,%2,%3},{%4,%5,%6,%7},{%8,%9},{%0,%1,%2,%3};" \
                 : "+f"((d)[0]), "+f"((d)[1]), "+f"((d)[2]), "+f"((d)[3]) \
                 : "r"((a)[0]), "r"((a)[1]), "r"((a)[2]), "r"((a)[3]), \
                   "r"((b)[0]), "r"((b)[1]))

// SW128 swizzle for 128-byte rows: off ^= (off>>3)&0x70
__device__ __forceinline__ uint32_t sw128(uint32_t base, int row, int ch) {
    uint32_t off = (uint32_t)(row * 128 + ch * 16);
    return base + (off ^ ((off >> 3) & 0x70));
}

// ---------------------------------------------------------------------------
// Aux kernels
// ---------------------------------------------------------------------------
__global__ void cvt_f2h_kernel(const float* __restrict__ s, __half* __restrict__ d) {
    size_t i = ((size_t)blockIdx.x * 256 + threadIdx.x) * 4;
    float4 v = *(const float4*)(s + i);
    *(__half2*)(d + i)     = __floats2half2_rn(v.x, v.y);
    *(__half2*)(d + i + 2) = __floats2half2_rn(v.z, v.w);
}

// Fused: x fp32 -> fp16 conversion + column partial sums (256-row chunks).
// grid (D/1024, B, 8), 256 threads; thread owns 4 consecutive columns.
__global__ void cvt_mean_kernel(const float* __restrict__ x, __half* __restrict__ xh) {
    int d0 = blockIdx.x * 1024 + threadIdx.x * 4;
    int b  = blockIdx.y;
    int c  = blockIdx.z;
    size_t base = ((size_t)(b * S_DIM + c * 256)) * D_DIM + d0;
    float s0 = 0.f, s1 = 0.f, s2 = 0.f, s3 = 0.f;
#pragma unroll 4
    for (int i = 0; i < 256; i++) {
        float4 v = *(const float4*)(x + base + (size_t)i * D_DIM);
        s0 += v.x; s1 += v.y; s2 += v.z; s3 += v.w;
        *(__half2*)(xh + base + (size_t)i * D_DIM)     = __floats2half2_rn(v.x, v.y);
        *(__half2*)(xh + base + (size_t)i * D_DIM + 2) = __floats2half2_rn(v.z, v.w);
    }
    float4 s = { s0, s1, s2, s3 };
    *(float4*)(g_partial + (b * 8 + c) * D_DIM + d0) = s;
}

__global__ void router_kernel(const float* __restrict__ rw, const float* __restrict__ rb) {
    int b = blockIdx.x;
    int tid = threadIdx.x;
    float acc[K_EXP];
#pragma unroll
    for (int k = 0; k < K_EXP; k++) acc[k] = 0.f;

    for (int d = tid; d < D_DIM; d += 256) {
        float m = 0.f;
#pragma unroll
        for (int c = 0; c < 8; c++) m += g_partial[(b * 8 + c) * D_DIM + d];
        m *= (1.0f / (float)S_DIM);
#pragma unroll
        for (int k = 0; k < K_EXP; k++) acc[k] += m * rw[k * D_DIM + d];
    }

    __shared__ float red[K_EXP][256];
#pragma unroll
    for (int k = 0; k < K_EXP; k++) red[k][tid] = acc[k];
    __syncthreads();

    if (tid < K_EXP) {
        float s = 0.f;
        for (int i = 0; i < 256; i++) s += red[tid][i];
        red[tid][0] = s + rb[tid];
    }
    __syncthreads();

    if (tid == 0) {
        float mx = -1e30f;
#pragma unroll
        for (int k = 0; k < K_EXP; k++) mx = fmaxf(mx, red[k][0]);
        float e[K_EXP], sum = 0.f;
#pragma unroll
        for (int k = 0; k < K_EXP; k++) { e[k] = expf(red[k][0] - mx); sum += e[k]; }
        float inv = 1.0f / sum;
#pragma unroll
        for (int k = 0; k < K_EXP; k++) g_weights[b * K_EXP + k] = e[k] * inv;
    }
}

__global__ void bw_kernel(const float* __restrict__ loraB) {
    int idx = blockIdx.x * 256 + threadIdx.x;           // < 2^21
    int b   = idx >> 19;
    int rem = idx & ((1 << 19) - 1);
    int o   = rem >> 7;
    int c   = rem & 127;
    int k   = c >> 4;
    int r   = c & 15;
    float v = SCALE * g_weights[b * K_EXP + k] * loraB[(k * D_DIM + o) * R_DIM + r];
    g_Bwh[idx] = __float2half_rn(v);
}

// reduce split-K partials of h -> fp16
__global__ void h_reduce_kernel() {
    size_t i = (size_t)blockIdx.x * 256 + threadIdx.x;   // over T_TOK*KR/2 half2s
    float2 a = *(const float2*)(g_hp[0] + 2 * i);
    float2 b = *(const float2*)(g_hp[1] + 2 * i);
    *(__half2*)(g_hh + 2 * i) = __floats2half2_rn(a.x + b.x, a.y + b.y);
}

// ---------------------------------------------------------------------------
// Pipelined fp16 mma.sync GEMM. BK=64, 3-stage cp.async, warp tile 64x32.
//   C[i,j] = sum_k A[i,k]*Bm[j,k]  (+ EXT: sum_c A2[i,c]*B2[b(i),j,c]) (+ bias[j])
// blockIdx.z (SPLITZ) offsets A/Bm by z*iters*64 along K and selects outf plane.
// ---------------------------------------------------------------------------
template <int BM, int BN, bool EXT, bool BIAS, bool OUTH, bool SPLITZ>
__global__ void __launch_bounds__((BM / 64) * (BN / 32) * 32, 2) mma_gemm_kernel(
    const __half* __restrict__ A, int lda,
    const __half* __restrict__ Bm, int ldb,
    const __half* __restrict__ A2,
    const __half* __restrict__ B2all,
    const float* __restrict__ bias,
    float* __restrict__ outf, __half* __restrict__ outh,
    int ldc, int iters0, int iters)
{
    constexpr int WM = BM / 64;
    constexpr int WN = BN / 32;
    constexpr int THREADS = WM * WN * 32;
    constexpr int ABYT = BM * 128;           // bytes per A stage (BK=64 halfs)
    constexpr int STG  = (BM + BN) * 128;    // bytes per stage

    extern __shared__ __align__(128) char smem[];
    const uint32_t sbase = smem_u32(smem);
    const int tid  = threadIdx.x;
    const int lane = tid & 31;
    const int wid  = tid >> 5;
    const int wm   = wid % WM;
    const int wn   = wid / WM;
    const int i0   = blockIdx.y * BM;
    const int j0   = blockIdx.x * BN;
    if (SPLITZ) {
        int zo = blockIdx.z * iters * 64;
        A  += zo;
        Bm += zo;
        outf += (size_t)blockIdx.z * ((size_t)T_TOK * KR);
    }
    const __half* B2 = nullptr;
    if (EXT) B2 = B2all + (size_t)(i0 >> 11) * ((size_t)D_DIM * KR);

    auto loadst = [&](int git, int st) {
        uint32_t abase = sbase + st * STG;
        uint32_t bbase = abase + ABYT;
        bool ph0 = (!EXT || git < iters0);
        int koff = ph0 ? git * 64 : (git - iters0) * 64;
#pragma unroll
        for (int t = 0; t < (BM * 8) / THREADS; t++) {
            int idx = tid + t * THREADS;
            int row = idx >> 3, ch = idx & 7;
            const __half* src = ph0
                ? A  + (size_t)(i0 + row) * lda + koff + ch * 8
                : A2 + (size_t)(i0 + row) * KR  + koff + ch * 8;
            CP_ASYNC16(sw128(abase, row, ch), src);
        }
#pragma unroll
        for (int t = 0; t < (BN * 8) / THREADS; t++) {
            int idx = tid + t * THREADS;
            int row = idx >> 3, ch = idx & 7;
            const __half* src = ph0
                ? Bm + (size_t)(j0 + row) * ldb + koff + ch * 8
                : B2 + (size_t)(j0 + row) * KR  + koff + ch * 8;
            CP_ASYNC16(sw128(bbase, row, ch), src);
        }
    };

    float acc[4][4][4];
#pragma unroll
    for (int mi = 0; mi < 4; mi++)
#pragma unroll
        for (int ni = 0; ni < 4; ni++)
#pragma unroll
            for (int e = 0; e < 4; e++) acc[mi][ni][e] = 0.f;

    // prologue: 2 stages in flight (3-stage ring)
    loadst(0, 0); CP_COMMIT();
    loadst(1, 1); CP_COMMIT();

    int st = 0;
    int pf = 2;
    for (int it = 0; it < iters; ++it) {
        CP_WAIT(1);
        __syncthreads();           // orders prev-iter reads before pf-stage writes
        if (it + 2 < iters) loadst(it + 2, pf);
        CP_COMMIT();

        uint32_t sA = sbase + st * STG;
        uint32_t sB = sA + ABYT;
#pragma unroll
        for (int ks = 0; ks < 4; ks++) {
            int ch = ks * 2 + (lane >> 4);
            uint32_t a[4][4];
#pragma unroll
            for (int mi = 0; mi < 4; mi++) {
                int row = wm * 64 + mi * 16 + (lane & 15);
                LDSM4(a[mi][0], a[mi][1], a[mi][2], a[mi][3], sw128(sA, row, ch));
            }
            uint32_t b[4][2];
#pragma unroll
            for (int j = 0; j < 2; j++) {
                int row = wn * 32 + j * 16 + (lane & 15);
                uint32_t t0, t1, t2, t3;
                LDSM4(t0, t1, t2, t3, sw128(sB, row, ch));
                b[2 * j][0]     = t0; b[2 * j][1]     = t2;
                b[2 * j + 1][0] = t1; b[2 * j + 1][1] = t3;
            }
#pragma unroll
            for (int mi = 0; mi < 4; mi++)
#pragma unroll
                for (int ni = 0; ni < 4; ni++)
                    MMA16816(acc[mi][ni], a[mi], b[ni]);
        }
        // no trailing barrier: next iter's top barrier orders reads vs writes
        st = (st == 2) ? 0 : st + 1;
        pf = (pf == 2) ? 0 : pf + 1;
    }

    // epilogue
#pragma unroll
    for (int mi = 0; mi < 4; mi++) {
        int r0 = i0 + wm * 64 + mi * 16 + (lane >> 2);
#pragma unroll
        for (int ni = 0; ni < 4; ni++) {
            int c0 = j0 + wn * 32 + ni * 8 + 2 * (lane & 3);
            if (OUTH) {
                *(__half2*)(outh + (size_t)r0 * ldc + c0) =
                    __floats2half2_rn(acc[mi][ni][0], acc[mi][ni][1]);
                *(__half2*)(outh + (size_t)(r0 + 8) * ldc + c0) =
                    __floats2half2_rn(acc[mi][ni][2], acc[mi][ni][3]);
            } else {
                float b0 = 0.f, b1 = 0.f;
                if (BIAS) { b0 = bias[c0]; b1 = bias[c0 + 1]; }
                float2 v0 = { acc[mi][ni][0] + b0, acc[mi][ni][1] + b1 };
                float2 v1 = { acc[mi][ni][2] + b0, acc[mi][ni][3] + b1 };
                *(float2*)(outf + (size_t)r0 * ldc + c0)       = v0;
                *(float2*)(outf + (size_t)(r0 + 8) * ldc + c0) = v1;
            }
        }
    }
}

// ---------------------------------------------------------------------------
extern "C" void kernel_launch(void* const* d_in, const int* in_sizes, int n_in,
                              void* d_out, int out_size) {
    const float* x      = (const float*)d_in[0];   // [4,2048,4096]
    const float* base_w = (const float*)d_in[1];   // [4096,4096]
    const float* base_b = (const float*)d_in[2];   // [4096]
    const float* lora_A = (const float*)d_in[3];   // [8,16,4096]
    const float* lora_B = (const float*)d_in[4];   // [8,4096,16]
    const float* rout_w = (const float*)d_in[5];   // [8,4096]
    const float* rout_b = (const float*)d_in[6];   // [8]
    float* out = (float*)d_out;

    const int SMEM_MAIN = 3 * (128 + 128) * 128;   // 98304
    const int SMEM_H    = 3 * (64 + 128) * 128;    // 73728
    cudaFuncSetAttribute(mma_gemm_kernel<128, 128, true, true, false, false>,
                         cudaFuncAttributeMaxDynamicSharedMemorySize, SMEM_MAIN);
    cudaFuncSetAttribute(mma_gemm_kernel<64, 128, false, false, false, true>,
                         cudaFuncAttributeMaxDynamicSharedMemorySize, SMEM_H);

    __half* xh;  cudaGetSymbolAddress((void**)&xh,  g_xh);
    __half* wh;  cudaGetSymbolAddress((void**)&wh,  g_wh);
    __half* ah;  cudaGetSymbolAddress((void**)&ah,  g_ah);
    __half* bwh; cudaGetSymbolAddress((void**)&bwh, g_Bwh);
    __half* hh;  cudaGetSymbolAddress((void**)&hh,  g_hh);
    float*  hp;  cudaGetSymbolAddress((void**)&hp,  g_hp);

    // fused x convert + mean partials; separate converts for W, lora_A
    cvt_mean_kernel<<<dim3(D_DIM / 1024, B_DIM, 8), 256>>>(x, xh);
    cvt_f2h_kernel<<<((size_t)D_DIM * D_DIM) / 1024, 256>>>(base_w, wh);
    cvt_f2h_kernel<<<((size_t)KR * D_DIM) / 1024, 256>>>(lora_A, ah);

    router_kernel<<<B_DIM, 256>>>(rout_w, rout_b);
    bw_kernel<<<(B_DIM * D_DIM * KR) / 256, 256>>>(lora_B);

    // h = x @ A_cat^T  split-K2 -> fp32 partials -> fp16
    mma_gemm_kernel<64, 128, false, false, false, true>
        <<<dim3(1, T_TOK / 64, 2), 128, SMEM_H>>>(
        xh, D_DIM, ah, D_DIM, nullptr, nullptr, nullptr,
        hp, nullptr, KR, 32, 32);
    h_reduce_kernel<<<(T_TOK * KR / 2) / 256, 256>>>();

    // out = x @ W^T + h @ Bw^T + bias  (K = 4096 + 128 => 64+2 iters of 64)
    mma_gemm_kernel<128, 128, true, true, false, false>
        <<<dim3(D_DIM / 128, T_TOK / 128), 256, SMEM_MAIN>>>(
        xh, D_DIM, wh, D_DIM, hh, bwh, base_b,
        out, nullptr, D_DIM, 64, 66);
}

// round 7
// speedup vs baseline: 1.2002x; 1.0506x over previous
#include <cuda_runtime.h>
#include <cuda_fp16.h>
#include <cstdint>
#include <math.h>

// ---------------- Problem constants ----------------
#define D_DIM 4096
#define S_DIM 2048
#define B_DIM 4
#define K_EXP 8
#define R_DIM 16
#define KR    128
#define T_TOK 8192
#define SCALE 2.0f
#define NCHUNK 32          // mean-pool chunks (64 rows each)

// ---------------- Device scratch (static; no runtime alloc) ----------------
__device__ __align__(16) float  g_partial[B_DIM * NCHUNK * D_DIM];    // 2 MB
__device__ __align__(16) float  g_lp[B_DIM * 16 * K_EXP];             // partial logits
__device__ float  g_weights[B_DIM * K_EXP];
__device__ __align__(16) __half g_xh[(size_t)T_TOK * D_DIM];          // 64 MB
__device__ __align__(16) __half g_wh[(size_t)D_DIM * D_DIM];          // 32 MB
__device__ __align__(16) __half g_ah[(size_t)KR * D_DIM];             //  1 MB
__device__ __align__(16) __half g_Bwh[(size_t)B_DIM * D_DIM * KR];    //  4 MB
__device__ __align__(16) __half g_hh[(size_t)T_TOK * KR];             //  2 MB
__device__ __align__(16) float  g_hp[2][(size_t)T_TOK * KR];          //  8 MB

// ---------------- PTX helpers ----------------
__device__ __forceinline__ uint32_t smem_u32(const void* p) {
    uint32_t a;
    asm("{ .reg .u64 t; cvta.to.shared.u64 t, %1; cvt.u32.u64 %0, t; }"
        : "=r"(a) : "l"(p));
    return a;
}

#define CP_ASYNC16(dst, src) \
    asm volatile("cp.async.cg.shared.global [%0], [%1], 16;" \
                 :: "r"(dst), "l"(src) : "memory")
#define CP_COMMIT() asm volatile("cp.async.commit_group;" ::: "memory")
#define CP_WAIT(n)  asm volatile("cp.async.wait_group %0;" :: "n"(n) : "memory")

#define LDSM4(r0, r1, r2, r3, addr) \
    asm volatile("ldmatrix.sync.aligned.m8n8.x4.shared.b16 {%0,%1,%2,%3}, [%4];" \
                 : "=r"(r0), "=r"(r1), "=r"(r2), "=r"(r3) : "r"(addr))

#define MMA16816(d, a, b) \
    asm volatile("mma.sync.aligned.m16n8k16.row.col.f32.f16.f16.f32 " \
                 "{%0,%1,%2,%3},{%4,%5,%6,%7},{%8,%9},{%0,%1,%2,%3};" \
                 : "+f"((d)[0]), "+f"((d)[1]), "+f"((d)[2]), "+f"((d)[3]) \
                 : "r"((a)[0]), "r"((a)[1]), "r"((a)[2]), "r"((a)[3]), \
                   "r"((b)[0]), "r"((b)[1]))

// SW128 swizzle for 128-byte rows
__device__ __forceinline__ uint32_t sw128(uint32_t base, int row, int ch) {
    uint32_t off = (uint32_t)(row * 128 + ch * 16);
    return base + (off ^ ((off >> 3) & 0x70));
}

// ---------------------------------------------------------------------------
// Aux kernels
// ---------------------------------------------------------------------------
__global__ void cvt_f2h_kernel(const float* __restrict__ s, __half* __restrict__ d) {
    size_t i = ((size_t)blockIdx.x * 256 + threadIdx.x) * 4;
    float4 v = *(const float4*)(s + i);
    *(__half2*)(d + i)     = __floats2half2_rn(v.x, v.y);
    *(__half2*)(d + i + 2) = __floats2half2_rn(v.z, v.w);
}

// Fused x fp32->fp16 + column partial sums over 64-row chunks.
__global__ void cvt_mean_kernel(const float* __restrict__ x, __half* __restrict__ xh) {
    int d0 = blockIdx.x * 1024 + threadIdx.x * 4;
    int b  = blockIdx.y;
    int c  = blockIdx.z;
    size_t base = ((size_t)(b * S_DIM + c * 64)) * D_DIM + d0;
    float s0 = 0.f, s1 = 0.f, s2 = 0.f, s3 = 0.f;
#pragma unroll 4
    for (int i = 0; i < 64; i++) {
        float4 v = *(const float4*)(x + base + (size_t)i * D_DIM);
        s0 += v.x; s1 += v.y; s2 += v.z; s3 += v.w;
        *(__half2*)(xh + base + (size_t)i * D_DIM)     = __floats2half2_rn(v.x, v.y);
        *(__half2*)(xh + base + (size_t)i * D_DIM + 2) = __floats2half2_rn(v.z, v.w);
    }
    float4 s = { s0, s1, s2, s3 };
    *(float4*)(g_partial + (b * NCHUNK + c) * D_DIM + d0) = s;
}

// Router phase A: partial logits per (b, slice of 256 d-columns)
__global__ void router_a_kernel(const float* __restrict__ rw) {
    int b = blockIdx.x;
    int s = blockIdx.y;
    int tid = threadIdx.x;
    int d = s * 256 + tid;

    float m = 0.f;
#pragma unroll
    for (int c = 0; c < NCHUNK; c++) m += g_partial[(b * NCHUNK + c) * D_DIM + d];
    m *= (1.0f / (float)S_DIM);

    __shared__ float red[256];
#pragma unroll
    for (int k = 0; k < K_EXP; k++) {
        red[tid] = m * rw[k * D_DIM + d];
        __syncthreads();
#pragma unroll
        for (int off = 128; off > 0; off >>= 1) {
            if (tid < off) red[tid] += red[tid + off];
            __syncthreads();
        }
        if (tid == 0) g_lp[(b * 16 + s) * K_EXP + k] = red[0];
        __syncthreads();
    }
}

// Router phase B: reduce slices + bias + softmax
__global__ void router_b_kernel(const float* __restrict__ rb) {
    int b = blockIdx.x;
    int tid = threadIdx.x;     // 32 threads
    __shared__ float lg[K_EXP];
    if (tid < K_EXP) {
        float s = 0.f;
#pragma unroll
        for (int q = 0; q < 16; q++) s += g_lp[(b * 16 + q) * K_EXP + tid];
        lg[tid] = s + rb[tid];
    }
    __syncwarp();
    if (tid == 0) {
        float mx = -1e30f;
#pragma unroll
        for (int k = 0; k < K_EXP; k++) mx = fmaxf(mx, lg[k]);
        float e[K_EXP], sum = 0.f;
#pragma unroll
        for (int k = 0; k < K_EXP; k++) { e[k] = expf(lg[k] - mx); sum += e[k]; }
        float inv = 1.0f / sum;
#pragma unroll
        for (int k = 0; k < K_EXP; k++) g_weights[b * K_EXP + k] = e[k] * inv;
    }
}

__global__ void bw_kernel(const float* __restrict__ loraB) {
    int idx = blockIdx.x * 256 + threadIdx.x;           // < 2^21
    int b   = idx >> 19;
    int rem = idx & ((1 << 19) - 1);
    int o   = rem >> 7;
    int c   = rem & 127;
    int k   = c >> 4;
    int r   = c & 15;
    float v = SCALE * g_weights[b * K_EXP + k] * loraB[(k * D_DIM + o) * R_DIM + r];
    g_Bwh[idx] = __float2half_rn(v);
}

__global__ void h_reduce_kernel() {
    size_t i = (size_t)blockIdx.x * 256 + threadIdx.x;
    float2 a = *(const float2*)(g_hp[0] + 2 * i);
    float2 b = *(const float2*)(g_hp[1] + 2 * i);
    *(__half2*)(g_hh + 2 * i) = __floats2half2_rn(a.x + b.x, a.y + b.y);
}

// ---------------------------------------------------------------------------
// h-GEMM: warp tile 64x32, BK=64, 3-stage (validated R6 config), split-K z.
// ---------------------------------------------------------------------------
__global__ void __launch_bounds__(128, 2) h_gemm_kernel(
    const __half* __restrict__ A, const __half* __restrict__ Bm,
    float* __restrict__ outf, int iters)
{
    constexpr int BM = 64, BN = 128;
    constexpr int THREADS = 128;
    constexpr int ABYT = BM * 128;
    constexpr int STG  = (BM + BN) * 128;

    extern __shared__ __align__(128) char smem[];
    const uint32_t sbase = smem_u32(smem);
    const int tid  = threadIdx.x;
    const int lane = tid & 31;
    const int wid  = tid >> 5;
    const int wn   = wid;                  // WM=1, 4 warps over N
    const int i0   = blockIdx.y * BM;
    const int zo   = blockIdx.z * iters * 64;
    A  += zo;
    Bm += zo;
    outf += (size_t)blockIdx.z * ((size_t)T_TOK * KR);

    auto loadst = [&](int git, int st) {
        uint32_t abase = sbase + st * STG;
        uint32_t bbase = abase + ABYT;
        int koff = git * 64;
#pragma unroll
        for (int t = 0; t < (BM * 8) / THREADS; t++) {
            int idx = tid + t * THREADS;
            int row = idx >> 3, ch = idx & 7;
            CP_ASYNC16(sw128(abase, row, ch),
                       A + (size_t)(i0 + row) * D_DIM + koff + ch * 8);
        }
#pragma unroll
        for (int t = 0; t < (BN * 8) / THREADS; t++) {
            int idx = tid + t * THREADS;
            int row = idx >> 3, ch = idx & 7;
            CP_ASYNC16(sw128(bbase, row, ch),
                       Bm + (size_t)row * D_DIM + koff + ch * 8);
        }
    };

    float acc[4][4][4];
#pragma unroll
    for (int mi = 0; mi < 4; mi++)
#pragma unroll
        for (int ni = 0; ni < 4; ni++)
#pragma unroll
            for (int e = 0; e < 4; e++) acc[mi][ni][e] = 0.f;

    loadst(0, 0); CP_COMMIT();
    loadst(1, 1); CP_COMMIT();

    int st = 0, pf = 2;
    for (int it = 0; it < iters; ++it) {
        CP_WAIT(1);
        __syncthreads();
        if (it + 2 < iters) loadst(it + 2, pf);
        CP_COMMIT();

        uint32_t sA = sbase + st * STG;
        uint32_t sB = sA + ABYT;
#pragma unroll
        for (int ks = 0; ks < 4; ks++) {
            int ch = ks * 2 + (lane >> 4);
            uint32_t a[4][4];
#pragma unroll
            for (int mi = 0; mi < 4; mi++) {
                int row = mi * 16 + (lane & 15);
                LDSM4(a[mi][0], a[mi][1], a[mi][2], a[mi][3], sw128(sA, row, ch));
            }
            uint32_t b[4][2];
#pragma unroll
            for (int j = 0; j < 2; j++) {
                int row = wn * 32 + j * 16 + (lane & 15);
                uint32_t t0, t1, t2, t3;
                LDSM4(t0, t1, t2, t3, sw128(sB, row, ch));
                b[2 * j][0]     = t0; b[2 * j][1]     = t2;
                b[2 * j + 1][0] = t1; b[2 * j + 1][1] = t3;
            }
#pragma unroll
            for (int mi = 0; mi < 4; mi++)
#pragma unroll
                for (int ni = 0; ni < 4; ni++)
                    MMA16816(acc[mi][ni], a[mi], b[ni]);
        }
        st = (st == 2) ? 0 : st + 1;
        pf = (pf == 2) ? 0 : pf + 1;
    }

#pragma unroll
    for (int mi = 0; mi < 4; mi++) {
        int r0 = i0 + mi * 16 + (lane >> 2);
#pragma unroll
        for (int ni = 0; ni < 4; ni++) {
            int c0 = wn * 32 + ni * 8 + 2 * (lane & 3);
            float2 v0 = { acc[mi][ni][0], acc[mi][ni][1] };
            float2 v1 = { acc[mi][ni][2], acc[mi][ni][3] };
            *(float2*)(outf + (size_t)r0 * KR + c0)       = v0;
            *(float2*)(outf + (size_t)(r0 + 8) * KR + c0) = v1;
        }
    }
}

// ---------------------------------------------------------------------------
// Main GEMM: BM=128, BN=256, BK=64, warp tile 64x64, 8 warps, 3-stage.
//   out = x@W^T (64 iters) + h@Bw^T (2 iters) + bias
// ---------------------------------------------------------------------------
__global__ void __launch_bounds__(256, 1) main_gemm_kernel(
    const __half* __restrict__ A,
    const __half* __restrict__ Bm,
    const __half* __restrict__ A2,
    const __half* __restrict__ B2all,
    const float* __restrict__ bias,
    float* __restrict__ outf)
{
    constexpr int BM = 128, BN = 256, THREADS = 256;
    constexpr int ITER0 = 64, ITERS = 66;
    constexpr int ABYT = BM * 128;           // 16 KB
    constexpr int STG  = (BM + BN) * 128;    // 48 KB

    extern __shared__ __align__(128) char smem[];
    const uint32_t sbase = smem_u32(smem);
    const int tid  = threadIdx.x;
    const int lane = tid & 31;
    const int wid  = tid >> 5;
    const int wm   = wid & 1;       // 2 warps over M
    const int wn   = wid >> 1;      // 4 warps over N (64 each)
    const int i0   = blockIdx.y * BM;
    const int j0   = blockIdx.x * BN;
    const __half* B2 = B2all + (size_t)(i0 >> 11) * ((size_t)D_DIM * KR);

    auto loadst = [&](int git, int st) {
        uint32_t abase = sbase + st * STG;
        uint32_t bbase = abase + ABYT;
        bool ph0 = (git < ITER0);
        int koff = ph0 ? git * 64 : (git - ITER0) * 64;
#pragma unroll
        for (int t = 0; t < (BM * 8) / THREADS; t++) {
            int idx = tid + t * THREADS;
            int row = idx >> 3, ch = idx & 7;
            const __half* src = ph0
                ? A  + (size_t)(i0 + row) * D_DIM + koff + ch * 8
                : A2 + (size_t)(i0 + row) * KR   + koff + ch * 8;
            CP_ASYNC16(sw128(abase, row, ch), src);
        }
#pragma unroll
        for (int t = 0; t < (BN * 8) / THREADS; t++) {
            int idx = tid + t * THREADS;
            int row = idx >> 3, ch = idx & 7;
            const __half* src = ph0
                ? Bm + (size_t)(j0 + row) * D_DIM + koff + ch * 8
                : B2 + (size_t)(j0 + row) * KR   + koff + ch * 8;
            CP_ASYNC16(sw128(bbase, row, ch), src);
        }
    };

    float acc[4][8][4];
#pragma unroll
    for (int mi = 0; mi < 4; mi++)
#pragma unroll
        for (int ni = 0; ni < 8; ni++)
#pragma unroll
            for (int e = 0; e < 4; e++) acc[mi][ni][e] = 0.f;

    loadst(0, 0); CP_COMMIT();
    loadst(1, 1); CP_COMMIT();

    int st = 0, pf = 2;
    for (int it = 0; it < ITERS; ++it) {
        CP_WAIT(1);
        __syncthreads();
        if (it + 2 < ITERS) loadst(it + 2, pf);
        CP_COMMIT();

        uint32_t sA = sbase + st * STG;
        uint32_t sB = sA + ABYT;
#pragma unroll
        for (int ks = 0; ks < 4; ks++) {
            int ch = ks * 2 + (lane >> 4);
            uint32_t a[4][4];
#pragma unroll
            for (int mi = 0; mi < 4; mi++) {
                int row = wm * 64 + mi * 16 + (lane & 15);
                LDSM4(a[mi][0], a[mi][1], a[mi][2], a[mi][3], sw128(sA, row, ch));
            }
            uint32_t b[8][2];
#pragma unroll
            for (int j = 0; j < 4; j++) {
                int row = wn * 64 + j * 16 + (lane & 15);
                uint32_t t0, t1, t2, t3;
                LDSM4(t0, t1, t2, t3, sw128(sB, row, ch));
                b[2 * j][0]     = t0; b[2 * j][1]     = t2;
                b[2 * j + 1][0] = t1; b[2 * j + 1][1] = t3;
            }
#pragma unroll
            for (int mi = 0; mi < 4; mi++)
#pragma unroll
                for (int ni = 0; ni < 8; ni++)
                    MMA16816(acc[mi][ni], a[mi], b[ni]);
        }
        st = (st == 2) ? 0 : st + 1;
        pf = (pf == 2) ? 0 : pf + 1;
    }

    // epilogue: bias + write
#pragma unroll
    for (int mi = 0; mi < 4; mi++) {
        int r0 = i0 + wm * 64 + mi * 16 + (lane >> 2);
#pragma unroll
        for (int ni = 0; ni < 8; ni++) {
            int c0 = j0 + wn * 64 + ni * 8 + 2 * (lane & 3);
            float b0 = bias[c0], b1 = bias[c0 + 1];
            float2 v0 = { acc[mi][ni][0] + b0, acc[mi][ni][1] + b1 };
            float2 v1 = { acc[mi][ni][2] + b0, acc[mi][ni][3] + b1 };
            *(float2*)(outf + (size_t)r0 * D_DIM + c0)       = v0;
            *(float2*)(outf + (size_t)(r0 + 8) * D_DIM + c0) = v1;
        }
    }
}

// ---------------------------------------------------------------------------
extern "C" void kernel_launch(void* const* d_in, const int* in_sizes, int n_in,
                              void* d_out, int out_size) {
    const float* x      = (const float*)d_in[0];   // [4,2048,4096]
    const float* base_w = (const float*)d_in[1];   // [4096,4096]
    const float* base_b = (const float*)d_in[2];   // [4096]
    const float* lora_A = (const float*)d_in[3];   // [8,16,4096]
    const float* lora_B = (const float*)d_in[4];   // [8,4096,16]
    const float* rout_w = (const float*)d_in[5];   // [8,4096]
    const float* rout_b = (const float*)d_in[6];   // [8]
    float* out = (float*)d_out;

    const int SMEM_MAIN = 3 * (128 + 256) * 128;   // 147456
    const int SMEM_H    = 3 * (64 + 128) * 128;    //  73728
    cudaFuncSetAttribute(main_gemm_kernel,
                         cudaFuncAttributeMaxDynamicSharedMemorySize, SMEM_MAIN);
    cudaFuncSetAttribute(h_gemm_kernel,
                         cudaFuncAttributeMaxDynamicSharedMemorySize, SMEM_H);

    __half* xh;  cudaGetSymbolAddress((void**)&xh,  g_xh);
    __half* wh;  cudaGetSymbolAddress((void**)&wh,  g_wh);
    __half* ah;  cudaGetSymbolAddress((void**)&ah,  g_ah);
    __half* bwh; cudaGetSymbolAddress((void**)&bwh, g_Bwh);
    __half* hh;  cudaGetSymbolAddress((void**)&hh,  g_hh);
    float*  hp;  cudaGetSymbolAddress((void**)&hp,  g_hp);

    cvt_mean_kernel<<<dim3(D_DIM / 1024, B_DIM, NCHUNK), 256>>>(x, xh);
    cvt_f2h_kernel<<<((size_t)D_DIM * D_DIM) / 1024, 256>>>(base_w, wh);
    cvt_f2h_kernel<<<((size_t)KR * D_DIM) / 1024, 256>>>(lora_A, ah);

    router_a_kernel<<<dim3(B_DIM, 16), 256>>>(rout_w);
    router_b_kernel<<<B_DIM, 32>>>(rout_b);
    bw_kernel<<<(B_DIM * D_DIM * KR) / 256, 256>>>(lora_B);

    // h = x @ A_cat^T  split-K2 -> fp32 partials -> fp16
    h_gemm_kernel<<<dim3(1, T_TOK / 64, 2), 128, SMEM_H>>>(xh, ah, hp, 32);
    h_reduce_kernel<<<(T_TOK * KR / 2) / 256, 256>>>();

    // out = x @ W^T + h @ Bw^T + bias
    main_gemm_kernel<<<dim3(D_DIM / 256, T_TOK / 128), 256, SMEM_MAIN>>>(
        xh, wh, hh, bwh, base_b, out);
}

// round 8
// speedup vs baseline: 1.2690x; 1.0573x over previous
#include <cuda_runtime.h>
#include <cuda_fp16.h>
#include <cstdint>
#include <math.h>

// ---------------- Problem constants ----------------
#define D_DIM 4096
#define S_DIM 2048
#define B_DIM 4
#define K_EXP 8
#define R_DIM 16
#define KR    128
#define T_TOK 8192
#define SCALE 2.0f
#define NCHUNK 32          // mean-pool chunks (64 rows each)

// ---------------- Device scratch (static; no runtime alloc) ----------------
__device__ __align__(16) float  g_partial[B_DIM * NCHUNK * D_DIM];    // 2 MB
__device__ __align__(16) float  g_lp[B_DIM * 16 * K_EXP];             // partial logits
__device__ float  g_weights[B_DIM * K_EXP];
__device__ __align__(16) __half g_xh[(size_t)T_TOK * D_DIM];          // 64 MB
__device__ __align__(16) __half g_wh[(size_t)D_DIM * D_DIM];          // 32 MB
__device__ __align__(16) __half g_ah[(size_t)KR * D_DIM];             //  1 MB
__device__ __align__(16) __half g_Bwh[(size_t)B_DIM * D_DIM * KR];    //  4 MB
__device__ __align__(16) __half g_hh[(size_t)T_TOK * KR];             //  2 MB
__device__ __align__(16) float  g_hp[2][(size_t)T_TOK * KR];          //  8 MB

// ---------------- PTX helpers ----------------
__device__ __forceinline__ uint32_t smem_u32(const void* p) {
    uint32_t a;
    asm("{ .reg .u64 t; cvta.to.shared.u64 t, %1; cvt.u32.u64 %0, t; }"
        : "=r"(a) : "l"(p));
    return a;
}

#define CP_ASYNC16(dst, src) \
    asm volatile("cp.async.cg.shared.global [%0], [%1], 16;" \
                 :: "r"(dst), "l"(src) : "memory")
#define CP_COMMIT() asm volatile("cp.async.commit_group;" ::: "memory")
#define CP_WAIT(n)  asm volatile("cp.async.wait_group %0;" :: "n"(n) : "memory")

#define LDSM4(r0, r1, r2, r3, addr) \
    asm volatile("ldmatrix.sync.aligned.m8n8.x4.shared.b16 {%0,%1,%2,%3}, [%4];" \
                 : "=r"(r0), "=r"(r1), "=r"(r2), "=r"(r3) : "r"(addr))

#define MMA16816(d, a, b) \
    asm volatile("mma.sync.aligned.m16n8k16.row.col.f32.f16.f16.f32 " \
                 "{%0,%1,%2,%3},{%4,%5,%6,%7},{%8,%9},{%0,%1,%2,%3};" \
                 : "+f"((d)[0]), "+f"((d)[1]), "+f"((d)[2]), "+f"((d)[3]) \
                 : "r"((a)[0]), "r"((a)[1]), "r"((a)[2]), "r"((a)[3]), \
                   "r"((b)[0]), "r"((b)[1]))

// SW128 swizzle for 128-byte rows
__device__ __forceinline__ uint32_t sw128(uint32_t base, int row, int ch) {
    uint32_t off = (uint32_t)(row * 128 + ch * 16);
    return base + (off ^ ((off >> 3) & 0x70));
}

// ---------------------------------------------------------------------------
// Aux kernels
// ---------------------------------------------------------------------------
__global__ void cvt_f2h_kernel(const float* __restrict__ s, __half* __restrict__ d) {
    size_t i = ((size_t)blockIdx.x * 256 + threadIdx.x) * 4;
    float4 v = *(const float4*)(s + i);
    *(__half2*)(d + i)     = __floats2half2_rn(v.x, v.y);
    *(__half2*)(d + i + 2) = __floats2half2_rn(v.z, v.w);
}

// Fused x fp32->fp16 + column partial sums over 64-row chunks.
__global__ void cvt_mean_kernel(const float* __restrict__ x, __half* __restrict__ xh) {
    int d0 = blockIdx.x * 1024 + threadIdx.x * 4;
    int b  = blockIdx.y;
    int c  = blockIdx.z;
    size_t base = ((size_t)(b * S_DIM + c * 64)) * D_DIM + d0;
    float s0 = 0.f, s1 = 0.f, s2 = 0.f, s3 = 0.f;
#pragma unroll 4
    for (int i = 0; i < 64; i++) {
        float4 v = *(const float4*)(x + base + (size_t)i * D_DIM);
        s0 += v.x; s1 += v.y; s2 += v.z; s3 += v.w;
        *(__half2*)(xh + base + (size_t)i * D_DIM)     = __floats2half2_rn(v.x, v.y);
        *(__half2*)(xh + base + (size_t)i * D_DIM + 2) = __floats2half2_rn(v.z, v.w);
    }
    float4 s = { s0, s1, s2, s3 };
    *(float4*)(g_partial + (b * NCHUNK + c) * D_DIM + d0) = s;
}

// Router phase A: partial logits per (b, slice of 256 d-columns)
__global__ void router_a_kernel(const float* __restrict__ rw) {
    int b = blockIdx.x;
    int s = blockIdx.y;
    int tid = threadIdx.x;
    int d = s * 256 + tid;

    float m = 0.f;
#pragma unroll
    for (int c = 0; c < NCHUNK; c++) m += g_partial[(b * NCHUNK + c) * D_DIM + d];
    m *= (1.0f / (float)S_DIM);

    __shared__ float red[256];
#pragma unroll
    for (int k = 0; k < K_EXP; k++) {
        red[tid] = m * rw[k * D_DIM + d];
        __syncthreads();
#pragma unroll
        for (int off = 128; off > 0; off >>= 1) {
            if (tid < off) red[tid] += red[tid + off];
            __syncthreads();
        }
        if (tid == 0) g_lp[(b * 16 + s) * K_EXP + k] = red[0];
        __syncthreads();
    }
}

// Router phase B: reduce slices + bias + softmax
__global__ void router_b_kernel(const float* __restrict__ rb) {
    int b = blockIdx.x;
    int tid = threadIdx.x;     // 32 threads
    __shared__ float lg[K_EXP];
    if (tid < K_EXP) {
        float s = 0.f;
#pragma unroll
        for (int q = 0; q < 16; q++) s += g_lp[(b * 16 + q) * K_EXP + tid];
        lg[tid] = s + rb[tid];
    }
    __syncwarp();
    if (tid == 0) {
        float mx = -1e30f;
#pragma unroll
        for (int k = 0; k < K_EXP; k++) mx = fmaxf(mx, lg[k]);
        float e[K_EXP], sum = 0.f;
#pragma unroll
        for (int k = 0; k < K_EXP; k++) { e[k] = expf(lg[k] - mx); sum += e[k]; }
        float inv = 1.0f / sum;
#pragma unroll
        for (int k = 0; k < K_EXP; k++) g_weights[b * K_EXP + k] = e[k] * inv;
    }
}

__global__ void bw_kernel(const float* __restrict__ loraB) {
    int idx = blockIdx.x * 256 + threadIdx.x;           // < 2^21
    int b   = idx >> 19;
    int rem = idx & ((1 << 19) - 1);
    int o   = rem >> 7;
    int c   = rem & 127;
    int k   = c >> 4;
    int r   = c & 15;
    float v = SCALE * g_weights[b * K_EXP + k] * loraB[(k * D_DIM + o) * R_DIM + r];
    g_Bwh[idx] = __float2half_rn(v);
}

__global__ void h_reduce_kernel() {
    size_t i = (size_t)blockIdx.x * 256 + threadIdx.x;
    float2 a = *(const float2*)(g_hp[0] + 2 * i);
    float2 b = *(const float2*)(g_hp[1] + 2 * i);
    *(__half2*)(g_hh + 2 * i) = __floats2half2_rn(a.x + b.x, a.y + b.y);
}

// ---------------------------------------------------------------------------
// h-GEMM: warp tile 64x32, BK=64, 3-stage, split-K z (validated R6/R7 config).
// ---------------------------------------------------------------------------
__global__ void __launch_bounds__(128, 2) h_gemm_kernel(
    const __half* __restrict__ A, const __half* __restrict__ Bm,
    float* __restrict__ outf, int iters)
{
    constexpr int BM = 64, BN = 128;
    constexpr int THREADS = 128;
    constexpr int ABYT = BM * 128;
    constexpr int STG  = (BM + BN) * 128;

    extern __shared__ __align__(128) char smem[];
    const uint32_t sbase = smem_u32(smem);
    const int tid  = threadIdx.x;
    const int lane = tid & 31;
    const int wid  = tid >> 5;
    const int wn   = wid;                  // WM=1, 4 warps over N
    const int i0   = blockIdx.y * BM;
    const int zo   = blockIdx.z * iters * 64;
    A  += zo;
    Bm += zo;
    outf += (size_t)blockIdx.z * ((size_t)T_TOK * KR);

    auto loadst = [&](int git, int st) {
        uint32_t abase = sbase + st * STG;
        uint32_t bbase = abase + ABYT;
        int koff = git * 64;
#pragma unroll
        for (int t = 0; t < (BM * 8) / THREADS; t++) {
            int idx = tid + t * THREADS;
            int row = idx >> 3, ch = idx & 7;
            CP_ASYNC16(sw128(abase, row, ch),
                       A + (size_t)(i0 + row) * D_DIM + koff + ch * 8);
        }
#pragma unroll
        for (int t = 0; t < (BN * 8) / THREADS; t++) {
            int idx = tid + t * THREADS;
            int row = idx >> 3, ch = idx & 7;
            CP_ASYNC16(sw128(bbase, row, ch),
                       Bm + (size_t)row * D_DIM + koff + ch * 8);
        }
    };

    float acc[4][4][4];
#pragma unroll
    for (int mi = 0; mi < 4; mi++)
#pragma unroll
        for (int ni = 0; ni < 4; ni++)
#pragma unroll
            for (int e = 0; e < 4; e++) acc[mi][ni][e] = 0.f;

    loadst(0, 0); CP_COMMIT();
    loadst(1, 1); CP_COMMIT();

    int st = 0, pf = 2;
    for (int it = 0; it < iters; ++it) {
        CP_WAIT(1);
        __syncthreads();
        if (it + 2 < iters) loadst(it + 2, pf);
        CP_COMMIT();

        uint32_t sA = sbase + st * STG;
        uint32_t sB = sA + ABYT;
#pragma unroll
        for (int ks = 0; ks < 4; ks++) {
            int ch = ks * 2 + (lane >> 4);
            uint32_t a[4][4];
#pragma unroll
            for (int mi = 0; mi < 4; mi++) {
                int row = mi * 16 + (lane & 15);
                LDSM4(a[mi][0], a[mi][1], a[mi][2], a[mi][3], sw128(sA, row, ch));
            }
            uint32_t b[4][2];
#pragma unroll
            for (int j = 0; j < 2; j++) {
                int row = wn * 32 + j * 16 + (lane & 15);
                uint32_t t0, t1, t2, t3;
                LDSM4(t0, t1, t2, t3, sw128(sB, row, ch));
                b[2 * j][0]     = t0; b[2 * j][1]     = t2;
                b[2 * j + 1][0] = t1; b[2 * j + 1][1] = t3;
            }
#pragma unroll
            for (int mi = 0; mi < 4; mi++)
#pragma unroll
                for (int ni = 0; ni < 4; ni++)
                    MMA16816(acc[mi][ni], a[mi], b[ni]);
        }
        st = (st == 2) ? 0 : st + 1;
        pf = (pf == 2) ? 0 : pf + 1;
    }

#pragma unroll
    for (int mi = 0; mi < 4; mi++) {
        int r0 = i0 + mi * 16 + (lane >> 2);
#pragma unroll
        for (int ni = 0; ni < 4; ni++) {
            int c0 = wn * 32 + ni * 8 + 2 * (lane & 3);
            float2 v0 = { acc[mi][ni][0], acc[mi][ni][1] };
            float2 v1 = { acc[mi][ni][2], acc[mi][ni][3] };
            *(float2*)(outf + (size_t)r0 * KR + c0)       = v0;
            *(float2*)(outf + (size_t)(r0 + 8) * KR + c0) = v1;
        }
    }
}

// ---------------------------------------------------------------------------
// Main GEMM: BM=128, BN=128, BK=64, 4 warps (2x2 of 64x64), 128 threads,
// 3-stage ring (96 KB smem) -> 2 CTAs/SM for cross-CTA bubble hiding.
//   out = x@W^T (64 iters) + h@Bw^T (2 iters) + bias
// ---------------------------------------------------------------------------
__global__ void __launch_bounds__(128, 2) main_gemm_kernel(
    const __half* __restrict__ A,
    const __half* __restrict__ Bm,
    const __half* __restrict__ A2,
    const __half* __restrict__ B2all,
    const float* __restrict__ bias,
    float* __restrict__ outf)
{
    constexpr int BM = 128, BN = 128, THREADS = 128;
    constexpr int ITER0 = 64, ITERS = 66;
    constexpr int ABYT = BM * 128;           // 16 KB
    constexpr int STG  = (BM + BN) * 128;    // 32 KB

    extern __shared__ __align__(128) char smem[];
    const uint32_t sbase = smem_u32(smem);
    const int tid  = threadIdx.x;
    const int lane = tid & 31;
    const int wid  = tid >> 5;
    const int wm   = wid & 1;       // 2 warps over M (64 each)
    const int wn   = wid >> 1;      // 2 warps over N (64 each)
    const int i0   = blockIdx.y * BM;
    const int j0   = blockIdx.x * BN;
    const __half* B2 = B2all + (size_t)(i0 >> 11) * ((size_t)D_DIM * KR);

    auto loadst = [&](int git, int st) {
        uint32_t abase = sbase + st * STG;
        uint32_t bbase = abase + ABYT;
        bool ph0 = (git < ITER0);
        int koff = ph0 ? git * 64 : (git - ITER0) * 64;
#pragma unroll
        for (int t = 0; t < (BM * 8) / THREADS; t++) {
            int idx = tid + t * THREADS;
            int row = idx >> 3, ch = idx & 7;
            const __half* src = ph0
                ? A  + (size_t)(i0 + row) * D_DIM + koff + ch * 8
                : A2 + (size_t)(i0 + row) * KR   + koff + ch * 8;
            CP_ASYNC16(sw128(abase, row, ch), src);
        }
#pragma unroll
        for (int t = 0; t < (BN * 8) / THREADS; t++) {
            int idx = tid + t * THREADS;
            int row = idx >> 3, ch = idx & 7;
            const __half* src = ph0
                ? Bm + (size_t)(j0 + row) * D_DIM + koff + ch * 8
                : B2 + (size_t)(j0 + row) * KR   + koff + ch * 8;
            CP_ASYNC16(sw128(bbase, row, ch), src);
        }
    };

    float acc[4][8][4];
#pragma unroll
    for (int mi = 0; mi < 4; mi++)
#pragma unroll
        for (int ni = 0; ni < 8; ni++)
#pragma unroll
            for (int e = 0; e < 4; e++) acc[mi][ni][e] = 0.f;

    loadst(0, 0); CP_COMMIT();
    loadst(1, 1); CP_COMMIT();

    int st = 0, pf = 2;
    for (int it = 0; it < ITERS; ++it) {
        CP_WAIT(1);
        __syncthreads();
        if (it + 2 < ITERS) loadst(it + 2, pf);
        CP_COMMIT();

        uint32_t sA = sbase + st * STG;
        uint32_t sB = sA + ABYT;
#pragma unroll
        for (int ks = 0; ks < 4; ks++) {
            int ch = ks * 2 + (lane >> 4);
            uint32_t a[4][4];
#pragma unroll
            for (int mi = 0; mi < 4; mi++) {
                int row = wm * 64 + mi * 16 + (lane & 15);
                LDSM4(a[mi][0], a[mi][1], a[mi][2], a[mi][3], sw128(sA, row, ch));
            }
            uint32_t b[8][2];
#pragma unroll
            for (int j = 0; j < 4; j++) {
                int row = wn * 64 + j * 16 + (lane & 15);
                uint32_t t0, t1, t2, t3;
                LDSM4(t0, t1, t2, t3, sw128(sB, row, ch));
                b[2 * j][0]     = t0; b[2 * j][1]     = t2;
                b[2 * j + 1][0] = t1; b[2 * j + 1][1] = t3;
            }
#pragma unroll
            for (int mi = 0; mi < 4; mi++)
#pragma unroll
                for (int ni = 0; ni < 8; ni++)
                    MMA16816(acc[mi][ni], a[mi], b[ni]);
        }
        st = (st == 2) ? 0 : st + 1;
        pf = (pf == 2) ? 0 : pf + 1;
    }

    // epilogue: bias + write
#pragma unroll
    for (int mi = 0; mi < 4; mi++) {
        int r0 = i0 + wm * 64 + mi * 16 + (lane >> 2);
#pragma unroll
        for (int ni = 0; ni < 8; ni++) {
            int c0 = j0 + wn * 64 + ni * 8 + 2 * (lane & 3);
            float b0 = bias[c0], b1 = bias[c0 + 1];
            float2 v0 = { acc[mi][ni][0] + b0, acc[mi][ni][1] + b1 };
            float2 v1 = { acc[mi][ni][2] + b0, acc[mi][ni][3] + b1 };
            *(float2*)(outf + (size_t)r0 * D_DIM + c0)       = v0;
            *(float2*)(outf + (size_t)(r0 + 8) * D_DIM + c0) = v1;
        }
    }
}

// ---------------------------------------------------------------------------
extern "C" void kernel_launch(void* const* d_in, const int* in_sizes, int n_in,
                              void* d_out, int out_size) {
    const float* x      = (const float*)d_in[0];   // [4,2048,4096]
    const float* base_w = (const float*)d_in[1];   // [4096,4096]
    const float* base_b = (const float*)d_in[2];   // [4096]
    const float* lora_A = (const float*)d_in[3];   // [8,16,4096]
    const float* lora_B = (const float*)d_in[4];   // [8,4096,16]
    const float* rout_w = (const float*)d_in[5];   // [8,4096]
    const float* rout_b = (const float*)d_in[6];   // [8]
    float* out = (float*)d_out;

    const int SMEM_MAIN = 3 * (128 + 128) * 128;   // 98304 -> 2 CTA/SM
    const int SMEM_H    = 3 * (64 + 128) * 128;    // 73728
    cudaFuncSetAttribute(main_gemm_kernel,
                         cudaFuncAttributeMaxDynamicSharedMemorySize, SMEM_MAIN);
    cudaFuncSetAttribute(h_gemm_kernel,
                         cudaFuncAttributeMaxDynamicSharedMemorySize, SMEM_H);

    __half* xh;  cudaGetSymbolAddress((void**)&xh,  g_xh);
    __half* wh;  cudaGetSymbolAddress((void**)&wh,  g_wh);
    __half* ah;  cudaGetSymbolAddress((void**)&ah,  g_ah);
    __half* bwh; cudaGetSymbolAddress((void**)&bwh, g_Bwh);
    __half* hh;  cudaGetSymbolAddress((void**)&hh,  g_hh);
    float*  hp;  cudaGetSymbolAddress((void**)&hp,  g_hp);

    cvt_mean_kernel<<<dim3(D_DIM / 1024, B_DIM, NCHUNK), 256>>>(x, xh);
    cvt_f2h_kernel<<<((size_t)D_DIM * D_DIM) / 1024, 256>>>(base_w, wh);
    cvt_f2h_kernel<<<((size_t)KR * D_DIM) / 1024, 256>>>(lora_A, ah);

    router_a_kernel<<<dim3(B_DIM, 16), 256>>>(rout_w);
    router_b_kernel<<<B_DIM, 32>>>(rout_b);
    bw_kernel<<<(B_DIM * D_DIM * KR) / 256, 256>>>(lora_B);

    // h = x @ A_cat^T  split-K2 -> fp32 partials -> fp16
    h_gemm_kernel<<<dim3(1, T_TOK / 64, 2), 128, SMEM_H>>>(xh, ah, hp, 32);
    h_reduce_kernel<<<(T_TOK * KR / 2) / 256, 256>>>();

    // out = x @ W^T + h @ Bw^T + bias
    main_gemm_kernel<<<dim3(D_DIM / 128, T_TOK / 128), 128, SMEM_MAIN>>>(
        xh, wh, hh, bwh, base_b, out);
}